// round 10
// baseline (speedup 1.0000x reference)
#include <cuda_runtime.h>
#include <cuda_fp16.h>
#include <math.h>

#define BB    128
#define TT    2048
#define KD    128
#define VD    128
#define HD    300
#define ED    400
#define NV    33
#define G4    1200
#define SOS   5
#define STEPS 500
#define NTHR  1024
#define CLU   8
#define TRB   256    // value-transpose blocks
#define KTB   4096   // key-transpose tile blocks

// ---------------- persistent device data (read-only after init) ----------
__device__ float g_ge[NV * G4];   // emb @ W_ih[:, :400]^T + b_ih + b_hh
// fp16 copies, uint4-typed for guaranteed 16B alignment:
// keys  [b][k][t]  (t-minor), values [b][t][v] (v-minor)
__device__ uint4 g_keys4[(size_t)BB * KD * (TT / 8)];
__device__ uint4 g_vals4[(size_t)BB * TT * (VD / 8)];

union U4 { uint4 u; __half2 h[4]; };

__device__ __forceinline__ float sigf(float x) { return 1.f / (1.f + __expf(-x)); }
__device__ __forceinline__ float tanf_(float x) { return 2.f / (1.f + __expf(-2.f * x)) - 1.f; }

// ---------------- DSMEM helpers ----------------
__device__ __forceinline__ unsigned smem_u32(const void* p) {
    unsigned a;
    asm("{ .reg .u64 t; cvta.to.shared.u64 t, %1; cvt.u32.u64 %0, t; }"
        : "=r"(a) : "l"(p));
    return a;
}
__device__ __forceinline__ unsigned mapa_rank(unsigned a, unsigned r) {
    unsigned d;
    asm("mapa.shared::cluster.u32 %0, %1, %2;" : "=r"(d) : "r"(a), "r"(r));
    return d;
}
__device__ __forceinline__ float ldsc_f(unsigned a) {
    float v; asm volatile("ld.shared::cluster.f32 %0, [%1];" : "=f"(v) : "r"(a)); return v;
}
__device__ __forceinline__ int ldsc_i(unsigned a) {
    int v; asm volatile("ld.shared::cluster.s32 %0, [%1];" : "=r"(v) : "r"(a)); return v;
}
__device__ __forceinline__ void stsc_f(unsigned a, float v) {
    asm volatile("st.shared::cluster.f32 [%0], %1;" :: "r"(a), "f"(v));
}
#define CLUSTER_SYNC() do { \
    asm volatile("barrier.cluster.arrive.aligned;" ::: "memory"); \
    asm volatile("barrier.cluster.wait.aligned;" ::: "memory"); \
} while (0)

// ---------------- init: g_ge precompute + transposes ----------------
__global__ void init_kernel(const float* __restrict__ keys,
                            const float* __restrict__ values,
                            const float* __restrict__ emb,
                            const float* __restrict__ W_ih,
                            const float* __restrict__ b_ih,
                            const float* __restrict__ b_hh) {
    int blk = blockIdx.x, tid = threadIdx.x;
    __shared__ float e_s[ED];
    __shared__ __half hk[KD * 64];   // 16KB key transpose tile [k][t]

    if (blk < NV) {
        for (int i = tid; i < ED; i += blockDim.x) e_s[i] = emb[blk * ED + i];
        __syncthreads();
        int wid = tid >> 5, lane = tid & 31;
        for (int j = wid; j < G4; j += 8) {
            float acc = 0.f;
            const float* wr = W_ih + (size_t)j * 528;
            for (int k = lane; k < ED; k += 32) acc += e_s[k] * wr[k];
            #pragma unroll
            for (int o = 16; o; o >>= 1) acc += __shfl_xor_sync(0xffffffffu, acc, o);
            if (lane == 0) g_ge[blk * G4 + j] = acc + b_ih[j] + b_hh[j];
        }
    } else if (blk < NV + TRB) {
        // values: [t][b][v] f32 -> [b][t][v] f16
        const int CH = TT * BB * VD / 8;
        int xb = blk - NV;
        for (int c = xb * blockDim.x + tid; c < CH; c += TRB * blockDim.x) {
            const float4* src = (const float4*)values + (size_t)c * 2;
            float4 a = src[0], b4 = src[1];
            U4 o;
            o.h[0] = __floats2half2_rn(a.x, a.y);
            o.h[1] = __floats2half2_rn(a.z, a.w);
            o.h[2] = __floats2half2_rn(b4.x, b4.y);
            o.h[3] = __floats2half2_rn(b4.z, b4.w);
            int kc = c & 15;
            int b  = (c >> 4) & 127;
            int t  = c >> 11;
            g_vals4[((size_t)b * TT + t) * 16 + kc] = o.u;
        }
    } else {
        // keys: [t][b][k] f32 -> [b][k][t] f16 via smem tile (64 t x 128 k)
        int bk = blk - (NV + TRB);           // 0..4095
        int b  = bk >> 5;
        int tt = (bk & 31) * 64;
        for (int idx = tid; idx < 64 * 32; idx += 256) {
            int t = idx >> 5, k4 = idx & 31;
            float4 v = __ldg((const float4*)(keys + ((size_t)(tt + t) * BB + b) * KD) + k4);
            int k = k4 * 4;
            hk[(k + 0) * 64 + t] = __float2half_rn(v.x);
            hk[(k + 1) * 64 + t] = __float2half_rn(v.y);
            hk[(k + 2) * 64 + t] = __float2half_rn(v.z);
            hk[(k + 3) * 64 + t] = __float2half_rn(v.w);
        }
        __syncthreads();
        for (int idx = tid; idx < 1024; idx += 256) {
            int k = idx >> 3, l8 = idx & 7;
            uint4 o = ((const uint4*)hk)[k * 8 + l8];
            g_keys4[((size_t)b * KD + k) * 256 + (tt >> 3) + l8] = o;
        }
    }
}

// ---------------- persistent kernel: cluster of 8 batches, no grid sync ----
__global__ void __launch_bounds__(NTHR, 1) __cluster_dims__(CLU, 1, 1)
decoder_persistent(const float* __restrict__ W_phi,
                   const float* __restrict__ b_phi,
                   const float* __restrict__ W_ih,
                   const float* __restrict__ W_hh,
                   const float* __restrict__ W_proj,
                   const float* __restrict__ b_proj,
                   const float* __restrict__ h0,
                   const float* __restrict__ c0,
                   float* __restrict__ out, int write_preds) {
    // smem: scratch union (attend: epart 8192 + w_s 2048 | lstm: xx 3456 + part 4864 + gs 1216)
    __shared__ __align__(16) float scr[10304];
    __shared__ __align__(16) float s_xin[432];    // [ctx 0:128, h 128:428]
    __shared__ __align__(16) float s_hnew[304];
    __shared__ float s_cst[304];                  // c for (8 batches x my 38-slice)
    __shared__ __align__(16) float s_q[128];
    __shared__ float s_lg[36];
    __shared__ float s_red[32];
    __shared__ float s_bc[2];
    __shared__ int   s_chr[8];
    __shared__ int   s_chrown;

    const int b    = blockIdx.x;          // batch
    const int rank = b & (CLU - 1);       // cluster rank
    const int tid  = threadIdx.x, wid = tid >> 5, lane = tid & 31;
    const int N0   = rank * 38;
    const int NR   = (300 - N0 < 38) ? (300 - N0) : 38;

    const unsigned a_xin = smem_u32(s_xin);
    const unsigned a_hnw = smem_u32(s_hnew);
    const unsigned a_chr = smem_u32(&s_chrown);

    // ---- initial state ----
    for (int i = tid; i < HD; i += NTHR) s_hnew[i] = h0[i];
    for (int o = tid; o < 304; o += NTHR) {
        int nl = o % 38;
        s_cst[o] = (nl < NR) ? c0[N0 + nl] : 0.f;
    }
    if (tid == 0) s_chrown = SOS;
    __syncthreads();

    for (int s = -1; s < STEPS; ++s) {
        // ================= LSTM (cluster-tiled), skipped for s == -1 =======
        if (s >= 0) {
            float* xx   = scr;            // [8][432]
            float* part = scr + 3456;     // 4864
            float* gs   = scr + 8320;     // 1216
            // stage x of all 8 batches + chars via DSMEM
            for (int i = 0; i < 8; i++) {
                unsigned ra = mapa_rank(a_xin, i);
                for (int k = tid; k < 428; k += NTHR)
                    xx[i * 432 + k] = ldsc_f(ra + k * 4);
            }
            if (tid < 8) s_chr[tid] = ldsc_i(mapa_rank(a_chr, tid));
            __syncthreads();

            // GEMM: 304 threads, tile 4 rows x 4 batches, k-split 4
            if (tid < 304) {
                int ks = tid / 76, rem = tid % 76;
                int rg = rem >> 1, bg = (rem & 1) * 4;
                float acc[4][4];
                #pragma unroll
                for (int r = 0; r < 4; r++)
                    #pragma unroll
                    for (int bi = 0; bi < 4; bi++) acc[r][bi] = 0.f;

                int rows[4];
                #pragma unroll
                for (int r = 0; r < 4; r++) {
                    int lr = rg * 4 + r;
                    int gq = lr / 38, nl = lr % 38;
                    int nle = (nl < NR) ? nl : (NR - 1);
                    rows[r] = gq * 300 + N0 + nle;
                }
                int k4s = ks * 27, k4e = (ks == 3) ? 107 : (k4s + 27);
                const float4* xb[4];
                #pragma unroll
                for (int bi = 0; bi < 4; bi++)
                    xb[bi] = (const float4*)(xx + (size_t)(bg + bi) * 432);

                int e1 = k4e < 32 ? k4e : 32;
                for (int k4 = k4s; k4 < e1; k4++) {
                    float4 w[4];
                    #pragma unroll
                    for (int r = 0; r < 4; r++)
                        w[r] = __ldg((const float4*)(W_ih + (size_t)rows[r] * 528 + 400) + k4);
                    #pragma unroll
                    for (int bi = 0; bi < 4; bi++) {
                        float4 x = xb[bi][k4];
                        #pragma unroll
                        for (int r = 0; r < 4; r++)
                            acc[r][bi] += w[r].x * x.x + w[r].y * x.y + w[r].z * x.z + w[r].w * x.w;
                    }
                }
                int s2 = k4s > 32 ? k4s : 32;
                for (int k4 = s2; k4 < k4e; k4++) {
                    float4 w[4];
                    #pragma unroll
                    for (int r = 0; r < 4; r++)
                        w[r] = __ldg((const float4*)(W_hh + (size_t)rows[r] * 300) + (k4 - 32));
                    #pragma unroll
                    for (int bi = 0; bi < 4; bi++) {
                        float4 x = xb[bi][k4];
                        #pragma unroll
                        for (int r = 0; r < 4; r++)
                            acc[r][bi] += w[r].x * x.x + w[r].y * x.y + w[r].z * x.z + w[r].w * x.w;
                    }
                }
                #pragma unroll
                for (int r = 0; r < 4; r++)
                    #pragma unroll
                    for (int bi = 0; bi < 4; bi++)
                        part[(rem * 16 + r * 4 + bi) * 4 + ks] = acc[r][bi];
            }
            __syncthreads();

            // reduce k-splits + g_ge bias
            for (int o = tid; o < 1216; o += NTHR) {
                float sum = part[o * 4] + part[o * 4 + 1] + part[o * 4 + 2] + part[o * 4 + 3];
                int rem = o >> 4, r = (o >> 2) & 3, bi = o & 3;
                int rg = rem >> 1, bg = (rem & 1) * 4;
                int lr = rg * 4 + r;
                int i  = bg + bi;
                int gq = lr / 38, nl = lr % 38;
                int nle = (nl < NR) ? nl : (NR - 1);
                int row = gq * 300 + N0 + nle;
                sum += g_ge[s_chr[i] * G4 + row];
                gs[i * 152 + lr] = sum;
            }
            __syncthreads();

            // gates -> c update + DSMEM h writes
            if (tid < 304) {
                int i = tid / 38, nl = tid % 38;
                if (nl < NR) {
                    float ig = sigf(gs[i * 152 + nl]);
                    float fg = sigf(gs[i * 152 + 38 + nl]);
                    float gg = tanf_(gs[i * 152 + 76 + nl]);
                    float og = sigf(gs[i * 152 + 114 + nl]);
                    float cn = fg * s_cst[tid] + ig * gg;
                    float hn = og * tanf_(cn);
                    s_cst[tid] = cn;
                    stsc_f(mapa_rank(a_hnw, i) + (N0 + nl) * 4, hn);
                }
            }
            __syncthreads();
            CLUSTER_SYNC();   // h_new complete in every CTA

            // ---- logits (h_new + ctx_old) + argmax ----
            for (int v = wid; v < NV; v += 32) {
                float acc = 0.f;
                const float* wr = W_proj + (size_t)v * 428;
                for (int k = lane; k < 428; k += 32) {
                    float x = (k < HD) ? s_hnew[k] : s_xin[k - HD];
                    acc += x * wr[k];
                }
                #pragma unroll
                for (int o = 16; o; o >>= 1) acc += __shfl_xor_sync(0xffffffffu, acc, o);
                if (lane == 0) s_lg[v] = acc + b_proj[v];
            }
            __syncthreads();
            if (tid < NV) out[(size_t)s * (BB * NV) + b * NV + tid] = s_lg[tid];
            if (tid == 0) {
                int am = 0; float mv = s_lg[0];
                for (int v = 1; v < NV; ++v) if (s_lg[v] > mv) { mv = s_lg[v]; am = v; }
                s_chrown = am;
                if (write_preds)
                    out[(size_t)STEPS * BB * NV + (size_t)s * BB + b] = (float)am;
            }
        }

        // ================= attend(h_new) ===================================
        // query = h @ W_phi^T + b_phi
        for (int q = wid; q < KD; q += 32) {
            float acc = 0.f;
            const float* wr = W_phi + (size_t)q * HD;
            for (int k = lane; k < HD; k += 32) acc += s_hnew[k] * wr[k];
            #pragma unroll
            for (int o = 16; o; o >>= 1) acc += __shfl_xor_sync(0xffffffffu, acc, o);
            if (lane == 0) s_q[q] = acc + b_phi[q];
        }
        __syncthreads();

        float* epart = scr;          // 8192
        float* cpart = scr;          // reuse
        float* w_s   = scr + 8192;   // 2048

        // energy pass: keys [b][k][t], lane owns 8 t, no shuffles
        {
            int ttile = (wid >> 2) * 256;
            int ks    = wid & 3;
            const uint4* kb = g_keys4 + ((size_t)b * KD + ks * 32) * 256
                            + (ttile >> 3) + lane;
            float e0=0,e1=0,e2=0,e3=0,e4=0,e5=0,e6=0,e7=0;
            #pragma unroll 8
            for (int k = 0; k < 32; k++) {
                U4 kv; kv.u = __ldcs(kb + (size_t)k * 256);
                float q = s_q[ks * 32 + k];
                float2 f0 = __half22float2(kv.h[0]);
                float2 f1 = __half22float2(kv.h[1]);
                float2 f2 = __half22float2(kv.h[2]);
                float2 f3 = __half22float2(kv.h[3]);
                e0 += q * f0.x; e1 += q * f0.y; e2 += q * f1.x; e3 += q * f1.y;
                e4 += q * f2.x; e5 += q * f2.y; e6 += q * f3.x; e7 += q * f3.y;
            }
            float4* ep = (float4*)(epart + ks * 2048 + ttile + lane * 8);
            ep[0] = make_float4(e0, e1, e2, e3);
            ep[1] = make_float4(e4, e5, e6, e7);
        }
        __syncthreads();

        // softmax
        float ea, eb;
        {
            int i0 = tid, i1 = tid + 1024;
            ea = epart[i0] + epart[2048 + i0] + epart[4096 + i0] + epart[6144 + i0];
            eb = epart[i1] + epart[2048 + i1] + epart[4096 + i1] + epart[6144 + i1];
            float m = fmaxf(ea, eb);
            #pragma unroll
            for (int o = 16; o; o >>= 1) m = fmaxf(m, __shfl_xor_sync(0xffffffffu, m, o));
            if (lane == 0) s_red[wid] = m;
        }
        __syncthreads();
        if (wid == 0) {
            float v = s_red[lane];
            #pragma unroll
            for (int o = 16; o; o >>= 1) v = fmaxf(v, __shfl_xor_sync(0xffffffffu, v, o));
            if (lane == 0) s_bc[0] = v;
        }
        __syncthreads();
        {
            float M = s_bc[0];
            float wa = __expf(ea - M), wb = __expf(eb - M);
            w_s[tid] = wa; w_s[tid + 1024] = wb;
            float ls = wa + wb;
            #pragma unroll
            for (int o = 16; o; o >>= 1) ls += __shfl_xor_sync(0xffffffffu, ls, o);
            if (lane == 0) s_red[wid] = ls;
        }
        __syncthreads();
        if (wid == 0) {
            float v = s_red[lane];
            #pragma unroll
            for (int o = 16; o; o >>= 1) v += __shfl_xor_sync(0xffffffffu, v, o);
            if (lane == 0) s_bc[1] = v;
        }
        __syncthreads();

        // value pass: values [b][t][v]
        {
            int kc = lane & 15, ts = lane >> 4;
            const uint4* vb = g_vals4 + (size_t)b * TT * 16;
            float va[8];
            #pragma unroll
            for (int j = 0; j < 8; j++) va[j] = 0.f;
            for (int t0 = wid * 8; t0 < TT; t0 += 256) {
                U4 vv[4]; float w[4];
                #pragma unroll
                for (int i = 0; i < 4; i++) {
                    int t = t0 + 2 * i + ts;
                    vv[i].u = __ldcs(&vb[(size_t)t * 16 + kc]);
                    w[i] = w_s[t];
                }
                #pragma unroll
                for (int i = 0; i < 4; i++) {
                    float2 f0 = __half22float2(vv[i].h[0]);
                    float2 f1 = __half22float2(vv[i].h[1]);
                    float2 f2 = __half22float2(vv[i].h[2]);
                    float2 f3 = __half22float2(vv[i].h[3]);
                    va[0] += w[i] * f0.x; va[1] += w[i] * f0.y;
                    va[2] += w[i] * f1.x; va[3] += w[i] * f1.y;
                    va[4] += w[i] * f2.x; va[5] += w[i] * f2.y;
                    va[6] += w[i] * f3.x; va[7] += w[i] * f3.y;
                }
            }
            #pragma unroll
            for (int j = 0; j < 8; j++)
                va[j] += __shfl_xor_sync(0xffffffffu, va[j], 16);
            if (ts == 0) {
                float4* cp = (float4*)(cpart + wid * 128 + kc * 8);
                cp[0] = make_float4(va[0], va[1], va[2], va[3]);
                cp[1] = make_float4(va[4], va[5], va[6], va[7]);
            }
        }
        __syncthreads();

        // ctx -> x_in[0:128]; h_new -> x_in[128:428]
        if (tid < 128) {
            float inv = 1.f / s_bc[1];
            float acc = 0.f;
            #pragma unroll
            for (int w = 0; w < 32; w++) acc += cpart[w * 128 + tid];
            s_xin[tid] = acc * inv;
        }
        for (int i = tid; i < HD; i += NTHR) s_xin[128 + i] = s_hnew[i];
        __syncthreads();
        CLUSTER_SYNC();   // x_in + char ready for next step's staging
    }
}

// ---------------- host launcher ----------------
extern "C" void kernel_launch(void* const* d_in, const int* in_sizes, int n_in,
                              void* d_out, int out_size) {
    const float* keys   = (const float*)d_in[0];
    const float* values = (const float*)d_in[1];
    const float* emb    = (const float*)d_in[2];
    const float* W_phi  = (const float*)d_in[3];
    const float* b_phi  = (const float*)d_in[4];
    const float* W_ih   = (const float*)d_in[5];
    const float* b_ih   = (const float*)d_in[6];
    const float* W_hh   = (const float*)d_in[7];
    const float* b_hh   = (const float*)d_in[8];
    const float* W_proj = (const float*)d_in[9];
    const float* b_proj = (const float*)d_in[10];
    const float* h0     = (const float*)d_in[11];
    const float* c0     = (const float*)d_in[12];
    float* out = (float*)d_out;

    int write_preds = (out_size >= STEPS * BB * NV + STEPS * BB) ? 1 : 0;

    init_kernel<<<NV + TRB + KTB, 256>>>(keys, values, emb, W_ih, b_ih, b_hh);
    decoder_persistent<<<BB, NTHR>>>(W_phi, b_phi, W_ih, W_hh, W_proj, b_proj,
                                     h0, c0, out, write_preds);
}

// round 12
// speedup vs baseline: 1.4931x; 1.4931x over previous
#include <cuda_runtime.h>
#include <cuda_fp16.h>
#include <math.h>

#define BB    128
#define TT    2048
#define KD    128
#define VD    128
#define HD    300
#define ED    400
#define NV    33
#define G4    1200
#define SOS   5
#define STEPS 500
#define NTHR  1024
#define TRB   256    // value-transpose blocks
#define KTB   4096   // key-transpose tile blocks
#define WQB   64     // weight-pack blocks
#define NK    428    // gemm k-dim

// ---------------- persistent device data (read-only after init) ----------
__device__ float4 g_geq[NV * HD];          // [char][n] = (i,f,g,o) emb-part+biases
__device__ float4 g_wf[NK * HD];           // [k][n] fp32 gate quad (i,f,g,o)
// fp16 copies: keys [b][k][t] (t-minor), values [b][t][v] (v-minor)
__device__ uint4 g_keys4[(size_t)BB * KD * (TT / 8)];
__device__ uint4 g_vals4[(size_t)BB * TT * (VD / 8)];

union U4 { uint4 u; __half2 h[4]; };

__device__ __forceinline__ float sigf(float x) { return 1.f / (1.f + __expf(-x)); }
__device__ __forceinline__ float tanf_(float x) { return 2.f / (1.f + __expf(-2.f * x)) - 1.f; }

// ---------------- init: precompute + transposes + fp32 weight pack -------
__global__ void init_kernel(const float* __restrict__ keys,
                            const float* __restrict__ values,
                            const float* __restrict__ emb,
                            const float* __restrict__ W_ih,
                            const float* __restrict__ b_ih,
                            const float* __restrict__ b_hh,
                            const float* __restrict__ W_hh) {
    int blk = blockIdx.x, tid = threadIdx.x;
    __shared__ float e_s[ED];
    __shared__ __half hk[KD * 64];   // 16KB key transpose tile [k][t]

    if (blk < NV) {
        for (int i = tid; i < ED; i += blockDim.x) e_s[i] = emb[blk * ED + i];
        __syncthreads();
        int wid = tid >> 5, lane = tid & 31;
        for (int j = wid; j < G4; j += 8) {
            float acc = 0.f;
            const float* wr = W_ih + (size_t)j * 528;
            for (int k = lane; k < ED; k += 32) acc += e_s[k] * wr[k];
            #pragma unroll
            for (int o = 16; o; o >>= 1) acc += __shfl_xor_sync(0xffffffffu, acc, o);
            if (lane == 0) {
                int g = j / 300, n = j % 300;
                ((float*)&g_geq[blk * HD + n])[g] = acc + b_ih[j] + b_hh[j];
            }
        }
    } else if (blk < NV + TRB) {
        // values: [t][b][v] f32 -> [b][t][v] f16
        const int CH = TT * BB * VD / 8;
        int xb = blk - NV;
        for (int c = xb * blockDim.x + tid; c < CH; c += TRB * blockDim.x) {
            const float4* src = (const float4*)values + (size_t)c * 2;
            float4 a = src[0], b4 = src[1];
            U4 o;
            o.h[0] = __floats2half2_rn(a.x, a.y);
            o.h[1] = __floats2half2_rn(a.z, a.w);
            o.h[2] = __floats2half2_rn(b4.x, b4.y);
            o.h[3] = __floats2half2_rn(b4.z, b4.w);
            int kc = c & 15;
            int b  = (c >> 4) & 127;
            int t  = c >> 11;
            g_vals4[((size_t)b * TT + t) * 16 + kc] = o.u;
        }
    } else if (blk < NV + TRB + KTB) {
        // keys: [t][b][k] f32 -> [b][k][t] f16 via smem tile (64 t x 128 k)
        int bk = blk - (NV + TRB);           // 0..4095
        int b  = bk >> 5;
        int tt = (bk & 31) * 64;
        for (int idx = tid; idx < 64 * 32; idx += 256) {
            int t = idx >> 5, k4 = idx & 31;
            float4 v = __ldg((const float4*)(keys + ((size_t)(tt + t) * BB + b) * KD) + k4);
            int k = k4 * 4;
            hk[(k + 0) * 64 + t] = __float2half_rn(v.x);
            hk[(k + 1) * 64 + t] = __float2half_rn(v.y);
            hk[(k + 2) * 64 + t] = __float2half_rn(v.z);
            hk[(k + 3) * 64 + t] = __float2half_rn(v.w);
        }
        __syncthreads();
        for (int idx = tid; idx < 1024; idx += 256) {
            int k = idx >> 3, l8 = idx & 7;
            uint4 o = ((const uint4*)hk)[k * 8 + l8];
            g_keys4[((size_t)b * KD + k) * 256 + (tt >> 3) + l8] = o;
        }
    } else {
        // pack LSTM weights fp32: g_wf[k*300+n] = (W[i], W[f], W[g], W[o]) at col k
        // k<128 -> W_ih[:, 400+k] (ctx part); k>=128 -> W_hh[:, k-128] (h part)
        int xb = blk - (NV + TRB + KTB);
        for (int e = xb * blockDim.x + tid; e < NK * HD; e += WQB * blockDim.x) {
            int k = e / HD, n = e % HD;
            float4 o;
            #pragma unroll
            for (int g = 0; g < 4; g++) {
                int row = g * 300 + n;
                float v = (k < 128) ? W_ih[(size_t)row * 528 + 400 + k]
                                    : W_hh[(size_t)row * 300 + (k - 128)];
                ((float*)&o)[g] = v;
            }
            g_wf[e] = o;
        }
    }
}

// ---------------- persistent kernel: one batch per CTA, ZERO barriers ----
__global__ void __launch_bounds__(NTHR, 1)
decoder_persistent(const float* __restrict__ W_phi,
                   const float* __restrict__ b_phi,
                   const float* __restrict__ W_proj,
                   const float* __restrict__ b_proj,
                   const float* __restrict__ h0,
                   const float* __restrict__ c0,
                   float* __restrict__ out, int write_preds) {
    // scratch union: attend epart 8192 + w_s 2048 | lstm part 3*1200=3600
    __shared__ __align__(16) float scr[10240];
    __shared__ __align__(16) float s_x[432];    // [ctx 0:128, h_old 128:428]
    __shared__ __align__(16) float s_h[304];    // h_new
    __shared__ __align__(16) float s_c[304];
    __shared__ __align__(16) float s_q[128];
    __shared__ float s_lg[36];
    __shared__ float s_red[32];
    __shared__ float s_bc[2];
    __shared__ int   s_char;

    const int b   = blockIdx.x;
    const int tid = threadIdx.x, wid = tid >> 5, lane = tid & 31;

    for (int i = tid; i < HD; i += NTHR) { s_h[i] = h0[i]; s_c[i] = c0[i]; }
    if (tid == 0) s_char = SOS;
    __syncthreads();

    for (int s = -1; s < STEPS; ++s) {
        if (s >= 0) {
            // ===== LSTM: gates = Wf(fp32 quad) @ x, k-split 3 (900 threads)
            float* part = scr;                    // [3][300] float4
            if (tid < 900) {
                int n = tid % 300, ks = tid / 300;
                int k0 = ks * 143;
                int k1 = (ks == 2) ? NK : (k0 + 143);
                float a0 = 0.f, a1 = 0.f, a2 = 0.f, a3 = 0.f;
                const float4* wp = g_wf + (size_t)k0 * HD + n;
                #pragma unroll 4
                for (int k = k0; k < k1; k++) {
                    float4 w = __ldg(wp); wp += HD;
                    float x = s_x[k];
                    a0 += x * w.x; a1 += x * w.y; a2 += x * w.z; a3 += x * w.w;
                }
                ((float4*)part)[ks * 300 + n] = make_float4(a0, a1, a2, a3);
            }
            __syncthreads();

            // reduce k-splits + emb/bias quad, activations, state update
            if (tid < 300) {
                float4 p0 = ((const float4*)part)[tid];
                float4 p1 = ((const float4*)part)[300 + tid];
                float4 p2 = ((const float4*)part)[600 + tid];
                float4 ge = g_geq[s_char * HD + tid];
                float gi = p0.x + p1.x + p2.x + ge.x;
                float gf = p0.y + p1.y + p2.y + ge.y;
                float gg = p0.z + p1.z + p2.z + ge.z;
                float go = p0.w + p1.w + p2.w + ge.w;
                float cn = sigf(gf) * s_c[tid] + sigf(gi) * tanf_(gg);
                float hn = sigf(go) * tanf_(cn);
                s_c[tid] = cn;
                s_h[tid] = hn;
            }
            __syncthreads();

            // ===== logits = [h_new, ctx_old] @ W_proj^T + b_proj; argmax
            for (int v = wid; v < NV; v += 32) {
                float acc = 0.f;
                const float* wr = W_proj + (size_t)v * 428;
                for (int k = lane; k < 428; k += 32) {
                    float x = (k < HD) ? s_h[k] : s_x[k - HD];
                    acc += x * wr[k];
                }
                #pragma unroll
                for (int o = 16; o; o >>= 1) acc += __shfl_xor_sync(0xffffffffu, acc, o);
                if (lane == 0) s_lg[v] = acc + b_proj[v];
            }
            __syncthreads();
            if (tid < NV) out[(size_t)s * (BB * NV) + b * NV + tid] = s_lg[tid];
            if (tid == 0) {
                int am = 0; float mv = s_lg[0];
                for (int v = 1; v < NV; ++v) if (s_lg[v] > mv) { mv = s_lg[v]; am = v; }
                s_char = am;
                if (write_preds)
                    out[(size_t)STEPS * BB * NV + (size_t)s * BB + b] = (float)am;
            }
        }

        // ===== attend(h_new) =============================================
        for (int q = wid; q < KD; q += 32) {
            float acc = 0.f;
            const float* wr = W_phi + (size_t)q * HD;
            for (int k = lane; k < HD; k += 32) acc += s_h[k] * wr[k];
            #pragma unroll
            for (int o = 16; o; o >>= 1) acc += __shfl_xor_sync(0xffffffffu, acc, o);
            if (lane == 0) s_q[q] = acc + b_phi[q];
        }
        __syncthreads();

        float* epart = scr;          // 8192
        float* cpart = scr;          // reuse after softmax
        float* w_s   = scr + 8192;   // 2048

        // energy pass: keys [b][k][t], lane owns 8 t, no shuffles
        {
            int ttile = (wid >> 2) * 256;
            int ks    = wid & 3;
            const uint4* kb = g_keys4 + ((size_t)b * KD + ks * 32) * 256
                            + (ttile >> 3) + lane;
            float e0=0,e1=0,e2=0,e3=0,e4=0,e5=0,e6=0,e7=0;
            #pragma unroll 8
            for (int k = 0; k < 32; k++) {
                U4 kv; kv.u = __ldg(kb + (size_t)k * 256);
                float q = s_q[ks * 32 + k];
                float2 f0 = __half22float2(kv.h[0]);
                float2 f1 = __half22float2(kv.h[1]);
                float2 f2 = __half22float2(kv.h[2]);
                float2 f3 = __half22float2(kv.h[3]);
                e0 += q * f0.x; e1 += q * f0.y; e2 += q * f1.x; e3 += q * f1.y;
                e4 += q * f2.x; e5 += q * f2.y; e6 += q * f3.x; e7 += q * f3.y;
            }
            float4* ep = (float4*)(epart + ks * 2048 + ttile + lane * 8);
            ep[0] = make_float4(e0, e1, e2, e3);
            ep[1] = make_float4(e4, e5, e6, e7);
        }
        __syncthreads();

        // softmax
        float ea, eb;
        {
            int i0 = tid, i1 = tid + 1024;
            ea = epart[i0] + epart[2048 + i0] + epart[4096 + i0] + epart[6144 + i0];
            eb = epart[i1] + epart[2048 + i1] + epart[4096 + i1] + epart[6144 + i1];
            float m = fmaxf(ea, eb);
            #pragma unroll
            for (int o = 16; o; o >>= 1) m = fmaxf(m, __shfl_xor_sync(0xffffffffu, m, o));
            if (lane == 0) s_red[wid] = m;
        }
        __syncthreads();
        if (wid == 0) {
            float v = s_red[lane];
            #pragma unroll
            for (int o = 16; o; o >>= 1) v = fmaxf(v, __shfl_xor_sync(0xffffffffu, v, o));
            if (lane == 0) s_bc[0] = v;
        }
        __syncthreads();
        {
            float M = s_bc[0];
            float wa = __expf(ea - M), wb = __expf(eb - M);
            w_s[tid] = wa; w_s[tid + 1024] = wb;
            float ls = wa + wb;
            #pragma unroll
            for (int o = 16; o; o >>= 1) ls += __shfl_xor_sync(0xffffffffu, ls, o);
            if (lane == 0) s_red[wid] = ls;
        }
        __syncthreads();
        if (wid == 0) {
            float v = s_red[lane];
            #pragma unroll
            for (int o = 16; o; o >>= 1) v += __shfl_xor_sync(0xffffffffu, v, o);
            if (lane == 0) s_bc[1] = v;
        }
        __syncthreads();

        // value pass: values [b][t][v]
        {
            int kc = lane & 15, ts = lane >> 4;
            const uint4* vb = g_vals4 + (size_t)b * TT * 16;
            float va[8];
            #pragma unroll
            for (int j = 0; j < 8; j++) va[j] = 0.f;
            for (int t0 = wid * 8; t0 < TT; t0 += 256) {
                U4 vv[4]; float w[4];
                #pragma unroll
                for (int i = 0; i < 4; i++) {
                    int t = t0 + 2 * i + ts;
                    vv[i].u = __ldg(&vb[(size_t)t * 16 + kc]);
                    w[i] = w_s[t];
                }
                #pragma unroll
                for (int i = 0; i < 4; i++) {
                    float2 f0 = __half22float2(vv[i].h[0]);
                    float2 f1 = __half22float2(vv[i].h[1]);
                    float2 f2 = __half22float2(vv[i].h[2]);
                    float2 f3 = __half22float2(vv[i].h[3]);
                    va[0] += w[i] * f0.x; va[1] += w[i] * f0.y;
                    va[2] += w[i] * f1.x; va[3] += w[i] * f1.y;
                    va[4] += w[i] * f2.x; va[5] += w[i] * f2.y;
                    va[6] += w[i] * f3.x; va[7] += w[i] * f3.y;
                }
            }
            #pragma unroll
            for (int j = 0; j < 8; j++)
                va[j] += __shfl_xor_sync(0xffffffffu, va[j], 16);
            if (ts == 0) {
                float4* cp = (float4*)(cpart + wid * 128 + kc * 8);
                cp[0] = make_float4(va[0], va[1], va[2], va[3]);
                cp[1] = make_float4(va[4], va[5], va[6], va[7]);
            }
        }
        __syncthreads();

        // ctx -> s_x[0:128]; h_new -> s_x[128:428]
        if (tid < 128) {
            float inv = 1.f / s_bc[1];
            float acc = 0.f;
            #pragma unroll
            for (int w = 0; w < 32; w++) acc += cpart[w * 128 + tid];
            s_x[tid] = acc * inv;
        }
        for (int i = tid; i < HD; i += NTHR) s_x[128 + i] = s_h[i];
        __syncthreads();
    }
}

// ---------------- host launcher ----------------
extern "C" void kernel_launch(void* const* d_in, const int* in_sizes, int n_in,
                              void* d_out, int out_size) {
    const float* keys   = (const float*)d_in[0];
    const float* values = (const float*)d_in[1];
    const float* emb    = (const float*)d_in[2];
    const float* W_phi  = (const float*)d_in[3];
    const float* b_phi  = (const float*)d_in[4];
    const float* W_ih   = (const float*)d_in[5];
    const float* b_ih   = (const float*)d_in[6];
    const float* W_hh   = (const float*)d_in[7];
    const float* b_hh   = (const float*)d_in[8];
    const float* W_proj = (const float*)d_in[9];
    const float* b_proj = (const float*)d_in[10];
    const float* h0     = (const float*)d_in[11];
    const float* c0     = (const float*)d_in[12];
    float* out = (float*)d_out;

    int write_preds = (out_size >= STEPS * BB * NV + STEPS * BB) ? 1 : 0;

    init_kernel<<<NV + TRB + KTB + WQB, 256>>>(keys, values, emb, W_ih, b_ih,
                                               b_hh, W_hh);
    decoder_persistent<<<BB, NTHR>>>(W_phi, b_phi, W_proj, b_proj,
                                     h0, c0, out, write_preds);
}

// round 13
// speedup vs baseline: 1.5094x; 1.0109x over previous
#include <cuda_runtime.h>
#include <cuda_fp16.h>
#include <math.h>

#define BB    128
#define TT    2048
#define KD    128
#define VD    128
#define HD    300
#define ED    400
#define NV    33
#define G4    1200
#define SOS   5
#define STEPS 500
#define NTHR  1024
#define TRB   256    // value-transpose blocks
#define KTB   4096   // key-transpose tile blocks
#define WQB   64     // weight-pack blocks
#define NK    428    // gemm k-dim
#define STG   65536  // TMA stage bytes
#define RING_OFF 16
#define SMEM_BYTES 162368

// ---------------- persistent device data (read-only after init) ----------
__device__ float4 g_geq[NV * HD];          // [char][n] = (i,f,g,o) emb-part+biases
__device__ float4 g_wf[NK * HD];           // [k][n] fp32 gate quad (i,f,g,o)
// fp16 copies: keys [b][k][t] (t-minor), values [b][t][v] (v-minor)
__device__ uint4 g_keys4[(size_t)BB * KD * (TT / 8)];
__device__ uint4 g_vals4[(size_t)BB * TT * (VD / 8)];

union U4 { uint4 u; __half2 h[4]; };

__device__ __forceinline__ float sigf(float x) { return 1.f / (1.f + __expf(-x)); }
__device__ __forceinline__ float tanf_(float x) { return 2.f / (1.f + __expf(-2.f * x)) - 1.f; }

// ---------------- smem/cluster/TMA helpers ----------------
__device__ __forceinline__ unsigned smem_u32(const void* p) {
    unsigned a;
    asm("{ .reg .u64 t; cvta.to.shared.u64 t, %1; cvt.u32.u64 %0, t; }"
        : "=r"(a) : "l"(p));
    return a;
}
__device__ __forceinline__ unsigned mapa_rank(unsigned a, unsigned r) {
    unsigned d;
    asm("mapa.shared::cluster.u32 %0, %1, %2;" : "=r"(d) : "r"(a), "r"(r));
    return d;
}
__device__ __forceinline__ float ldsc_f(unsigned a) {
    float v; asm volatile("ld.shared::cluster.f32 %0, [%1];" : "=f"(v) : "r"(a)); return v;
}
__device__ __forceinline__ int ldsc_i(unsigned a) {
    int v; asm volatile("ld.shared::cluster.s32 %0, [%1];" : "=r"(v) : "r"(a)); return v;
}
__device__ __forceinline__ void stsc_f(unsigned a, float v) {
    asm volatile("st.shared::cluster.f32 [%0], %1;" :: "r"(a), "f"(v));
}
#define CLUSTER_SYNC() do { \
    asm volatile("barrier.cluster.arrive.aligned;" ::: "memory"); \
    asm volatile("barrier.cluster.wait.aligned;" ::: "memory"); \
} while (0)

__device__ __forceinline__ void mbar_init(unsigned a, unsigned cnt) {
    asm volatile("mbarrier.init.shared.b64 [%0], %1;" :: "r"(a), "r"(cnt) : "memory");
}
__device__ __forceinline__ void mbar_expect_tx(unsigned a, unsigned bytes) {
    asm volatile("mbarrier.arrive.expect_tx.shared.b64 _, [%0], %1;"
                 :: "r"(a), "r"(bytes) : "memory");
}
__device__ __forceinline__ void tma_ld(unsigned dst, const void* src,
                                       unsigned bytes, unsigned mbar) {
    asm volatile("cp.async.bulk.shared::cluster.global.mbarrier::complete_tx::bytes "
                 "[%0], [%1], %2, [%3];"
                 :: "r"(dst), "l"(src), "r"(bytes), "r"(mbar) : "memory");
}
__device__ __forceinline__ void mbar_wait(unsigned mbar, int parity) {
    asm volatile(
        "{\n\t.reg .pred P;\n\t"
        "WL_%=:\n\t"
        "mbarrier.try_wait.parity.acquire.cta.shared::cta.b64 P, [%0], %1, 0x989680;\n\t"
        "@P bra.uni WD_%=;\n\t"
        "bra.uni WL_%=;\n\t"
        "WD_%=:\n\t}"
        :: "r"(mbar), "r"((unsigned)parity) : "memory");
}

// ---------------- init: precompute + transposes + fp32 weight pack -------
__global__ void init_kernel(const float* __restrict__ keys,
                            const float* __restrict__ values,
                            const float* __restrict__ emb,
                            const float* __restrict__ W_ih,
                            const float* __restrict__ b_ih,
                            const float* __restrict__ b_hh,
                            const float* __restrict__ W_hh) {
    int blk = blockIdx.x, tid = threadIdx.x;
    __shared__ float e_s[ED];
    __shared__ __half hk[KD * 64];

    if (blk < NV) {
        for (int i = tid; i < ED; i += blockDim.x) e_s[i] = emb[blk * ED + i];
        __syncthreads();
        int wid = tid >> 5, lane = tid & 31;
        for (int j = wid; j < G4; j += 8) {
            float acc = 0.f;
            const float* wr = W_ih + (size_t)j * 528;
            for (int k = lane; k < ED; k += 32) acc += e_s[k] * wr[k];
            #pragma unroll
            for (int o = 16; o; o >>= 1) acc += __shfl_xor_sync(0xffffffffu, acc, o);
            if (lane == 0) {
                int g = j / 300, n = j % 300;
                ((float*)&g_geq[blk * HD + n])[g] = acc + b_ih[j] + b_hh[j];
            }
        }
    } else if (blk < NV + TRB) {
        const int CH = TT * BB * VD / 8;
        int xb = blk - NV;
        for (int c = xb * blockDim.x + tid; c < CH; c += TRB * blockDim.x) {
            const float4* src = (const float4*)values + (size_t)c * 2;
            float4 a = src[0], b4 = src[1];
            U4 o;
            o.h[0] = __floats2half2_rn(a.x, a.y);
            o.h[1] = __floats2half2_rn(a.z, a.w);
            o.h[2] = __floats2half2_rn(b4.x, b4.y);
            o.h[3] = __floats2half2_rn(b4.z, b4.w);
            int kc = c & 15;
            int b  = (c >> 4) & 127;
            int t  = c >> 11;
            g_vals4[((size_t)b * TT + t) * 16 + kc] = o.u;
        }
    } else if (blk < NV + TRB + KTB) {
        int bk = blk - (NV + TRB);
        int b  = bk >> 5;
        int tt = (bk & 31) * 64;
        for (int idx = tid; idx < 64 * 32; idx += 256) {
            int t = idx >> 5, k4 = idx & 31;
            float4 v = __ldg((const float4*)(keys + ((size_t)(tt + t) * BB + b) * KD) + k4);
            int k = k4 * 4;
            hk[(k + 0) * 64 + t] = __float2half_rn(v.x);
            hk[(k + 1) * 64 + t] = __float2half_rn(v.y);
            hk[(k + 2) * 64 + t] = __float2half_rn(v.z);
            hk[(k + 3) * 64 + t] = __float2half_rn(v.w);
        }
        __syncthreads();
        for (int idx = tid; idx < 1024; idx += 256) {
            int k = idx >> 3, l8 = idx & 7;
            uint4 o = ((const uint4*)hk)[k * 8 + l8];
            g_keys4[((size_t)b * KD + k) * 256 + (tt >> 3) + l8] = o;
        }
    } else {
        int xb = blk - (NV + TRB + KTB);
        for (int e = xb * blockDim.x + tid; e < NK * HD; e += WQB * blockDim.x) {
            int k = e / HD, n = e % HD;
            float4 o;
            #pragma unroll
            for (int g = 0; g < 4; g++) {
                int row = g * 300 + n;
                float v = (k < 128) ? W_ih[(size_t)row * 528 + 400 + k]
                                    : W_hh[(size_t)row * 300 + (k - 128)];
                ((float*)&o)[g] = v;
            }
            g_wf[e] = o;
        }
    }
}

// ---------------- persistent kernel: batch/CTA, 2-CTA LSTM split, TMA ----
__global__ void __launch_bounds__(NTHR, 1) __cluster_dims__(2, 1, 1)
decoder_persistent(const float* __restrict__ W_phi,
                   const float* __restrict__ b_phi,
                   const float* __restrict__ W_proj,
                   const float* __restrict__ b_proj,
                   const float* __restrict__ h0,
                   const float* __restrict__ c0,
                   float* __restrict__ out, int write_preds) {
    extern __shared__ __align__(16) char dsm[];
    // [0,16): 2 mbarriers; [16, 16+2*STG): ring; then floats
    float* fb    = (float*)(dsm + RING_OFF + 2 * STG);
    float* w_s   = fb;            // 2048
    float* scr   = fb + 2048;     // 4096 (lstm part / cpart)
    float* s_x   = fb + 6144;     // 432  [ctx 0:128, h_old 128:428]
    float* s_xp  = fb + 6576;     // 432  partner x copy
    float* s_h   = fb + 7008;     // 304
    float* s_c   = fb + 7312;     // 304  c[2 batches][150 n-slice]
    float* s_q   = fb + 7616;     // 128
    float* s_lg  = fb + 7744;     // 36
    float* s_red = fb + 7780;     // 32
    float* s_bc  = fb + 7812;     // 2
    int*   s_chr = (int*)(fb + 7814); // [0]=own char, [1]=partner char

    const int b    = blockIdx.x;
    const int rank = b & 1;
    const int pr   = rank ^ 1;
    const int tid  = threadIdx.x, wid = tid >> 5, lane = tid & 31;

    const unsigned mb0 = smem_u32(dsm);
    const unsigned mb1 = mb0 + 8;
    const unsigned ring0 = smem_u32(dsm + RING_OFF);
    const unsigned a_sx  = smem_u32(s_x);
    const unsigned a_sh  = smem_u32(s_h);
    const unsigned a_chr = smem_u32(s_chr);
    const char* kbase = (const char*)g_keys4 + (size_t)b * 524288;
    const char* vbase = (const char*)g_vals4 + (size_t)b * 524288;

    if (tid == 0) { mbar_init(mb0, 1); mbar_init(mb1, 1); }
    for (int i = tid; i < HD; i += NTHR) s_h[i] = h0[i];
    if (tid < 300) s_c[tid] = c0[rank * 150 + (tid % 150)];
    if (tid == 0) s_chr[0] = SOS;
    __syncthreads();

    // prologue: prefetch key chunks 0,1 for the s=-1 attend
    if (tid == 0) {
        mbar_expect_tx(mb0, STG); tma_ld(ring0,       kbase,       STG, mb0);
        mbar_expect_tx(mb1, STG); tma_ld(ring0 + STG, kbase + STG, STG, mb1);
    }

    int ph0 = 0, ph1 = 0;

    for (int s = -1; s < STEPS; ++s) {
        if (s >= 0) {
            // ---- exchange partner x + char (covered by prev cluster sync)
            {
                unsigned pxa = mapa_rank(a_sx, pr);
                for (int k = tid; k < 428; k += NTHR) s_xp[k] = ldsc_f(pxa + k * 4);
                if (tid == 0) s_chr[1] = ldsc_i(mapa_rank(a_chr, pr));
            }
            __syncthreads();

            // ---- gate GEMM: n-slice [rank*150,150) for BOTH batches, k-split 3
            if (tid < 900) {
                int ks = tid / 300, r2 = tid % 300;
                int bsel = r2 / 150, nl = r2 % 150;
                int n = rank * 150 + nl;
                const float* xs = bsel ? s_xp : s_x;
                int k0 = ks * 143, k1 = (ks == 2) ? NK : (k0 + 143);
                float a0 = 0.f, a1 = 0.f, a2 = 0.f, a3 = 0.f;
                const float4* wp = g_wf + (size_t)k0 * HD + n;
                #pragma unroll 4
                for (int k = k0; k < k1; k++) {
                    float4 w = __ldg(wp); wp += HD;
                    float x = xs[k];
                    a0 += x * w.x; a1 += x * w.y; a2 += x * w.z; a3 += x * w.w;
                }
                ((float4*)scr)[ks * 300 + r2] = make_float4(a0, a1, a2, a3);
            }
            __syncthreads();

            // ---- reduce + activations; own half local, partner half via DSMEM
            if (tid < 300) {
                int bsel = tid / 150, nl = tid % 150;
                int n = rank * 150 + nl;
                float4 p0 = ((const float4*)scr)[tid];
                float4 p1 = ((const float4*)scr)[300 + tid];
                float4 p2 = ((const float4*)scr)[600 + tid];
                float4 ge = g_geq[s_chr[bsel] * HD + n];
                float gi = p0.x + p1.x + p2.x + ge.x;
                float gf = p0.y + p1.y + p2.y + ge.y;
                float gg = p0.z + p1.z + p2.z + ge.z;
                float go = p0.w + p1.w + p2.w + ge.w;
                float cn = sigf(gf) * s_c[tid] + sigf(gi) * tanf_(gg);
                float hn = sigf(go) * tanf_(cn);
                s_c[tid] = cn;
                if (bsel == 0) s_h[n] = hn;
                else           stsc_f(mapa_rank(a_sh, pr) + n * 4, hn);
            }
            __syncthreads();
            CLUSTER_SYNC();    // h_new complete in both CTAs

            // ---- logits = [h_new, ctx_old] @ W_proj^T; argmax
            for (int v = wid; v < NV; v += 32) {
                float acc = 0.f;
                const float* wr = W_proj + (size_t)v * 428;
                for (int k = lane; k < 428; k += 32) {
                    float x = (k < HD) ? s_h[k] : s_x[k - HD];
                    acc += x * wr[k];
                }
                #pragma unroll
                for (int o = 16; o; o >>= 1) acc += __shfl_xor_sync(0xffffffffu, acc, o);
                if (lane == 0) s_lg[v] = acc + b_proj[v];
            }
            __syncthreads();
            if (tid < NV) out[(size_t)s * (BB * NV) + b * NV + tid] = s_lg[tid];
            if (tid == 0) {
                int am = 0; float mv = s_lg[0];
                for (int v = 1; v < NV; ++v) if (s_lg[v] > mv) { mv = s_lg[v]; am = v; }
                s_chr[0] = am;
                if (write_preds)
                    out[(size_t)STEPS * BB * NV + (size_t)s * BB + b] = (float)am;
            }
        }
        if (s == STEPS - 1) break;   // final attend's ctx is never consumed

        // ================= attend(h_new) via TMA ring ======================
        for (int q = wid; q < KD; q += 32) {
            float acc = 0.f;
            const float* wr = W_phi + (size_t)q * HD;
            for (int k = lane; k < HD; k += 32) acc += s_h[k] * wr[k];
            #pragma unroll
            for (int o = 16; o; o >>= 1) acc += __shfl_xor_sync(0xffffffffu, acc, o);
            if (lane == 0) s_q[q] = acc + b_phi[q];
        }
        __syncthreads();

        // ---- energy: 8 key chunks (16 k-rows x 4KB); thread owns t=2tid,2tid+1
        float e0 = 0.f, e1 = 0.f;
        for (int c = 0; c < 8; c++) {
            int st = c & 1;
            unsigned mb = st ? mb1 : mb0;
            if (st) { mbar_wait(mb, ph1); ph1 ^= 1; }
            else    { mbar_wait(mb, ph0); ph0 ^= 1; }
            const __half2* buf = (const __half2*)(dsm + RING_OFF + st * STG);
            #pragma unroll
            for (int r = 0; r < 16; r++) {
                float2 kv = __half22float2(buf[r * 1024 + tid]);
                float q = s_q[c * 16 + r];
                e0 += q * kv.x;
                e1 += q * kv.y;
            }
            __syncthreads();
            if (tid == 0) {
                int nx = c + 2;
                unsigned dst = ring0 + st * STG;
                mbar_expect_tx(mb, STG);
                if (nx < 8) tma_ld(dst, kbase + (size_t)nx * STG, STG, mb);
                else        tma_ld(dst, vbase + (size_t)(nx - 8) * STG, STG, mb);
            }
        }

        // ---- softmax over per-thread (e0,e1)
        {
            float m = fmaxf(e0, e1);
            #pragma unroll
            for (int o = 16; o; o >>= 1) m = fmaxf(m, __shfl_xor_sync(0xffffffffu, m, o));
            if (lane == 0) s_red[wid] = m;
        }
        __syncthreads();
        if (wid == 0) {
            float v = s_red[lane];
            #pragma unroll
            for (int o = 16; o; o >>= 1) v = fmaxf(v, __shfl_xor_sync(0xffffffffu, v, o));
            if (lane == 0) s_bc[0] = v;
        }
        __syncthreads();
        {
            float M = s_bc[0];
            float w0 = __expf(e0 - M), w1 = __expf(e1 - M);
            ((float2*)w_s)[tid] = make_float2(w0, w1);
            float ls = w0 + w1;
            #pragma unroll
            for (int o = 16; o; o >>= 1) ls += __shfl_xor_sync(0xffffffffu, ls, o);
            if (lane == 0) s_red[wid] = ls;
        }
        __syncthreads();
        if (wid == 0) {
            float v = s_red[lane];
            #pragma unroll
            for (int o = 16; o; o >>= 1) v += __shfl_xor_sync(0xffffffffu, v, o);
            if (lane == 0) s_bc[1] = v;
        }
        __syncthreads();

        // ---- values: 8 chunks (256 t-rows x 256B); kc=v-chunk, tg=t-group
        {
            int kc = tid & 15, tg = tid >> 4;
            float va[8];
            #pragma unroll
            for (int j = 0; j < 8; j++) va[j] = 0.f;
            for (int c = 0; c < 8; c++) {
                int st = c & 1;
                unsigned mb = st ? mb1 : mb0;
                if (st) { mbar_wait(mb, ph1); ph1 ^= 1; }
                else    { mbar_wait(mb, ph0); ph0 ^= 1; }
                const char* buf = dsm + RING_OFF + st * STG;
                #pragma unroll
                for (int j = 0; j < 4; j++) {
                    int row = tg + 64 * j;
                    U4 vv; vv.u = *(const uint4*)(buf + row * 256 + kc * 16);
                    float w = w_s[c * 256 + row];
                    float2 f0 = __half22float2(vv.h[0]);
                    float2 f1 = __half22float2(vv.h[1]);
                    float2 f2 = __half22float2(vv.h[2]);
                    float2 f3 = __half22float2(vv.h[3]);
                    va[0] += w * f0.x; va[1] += w * f0.y;
                    va[2] += w * f1.x; va[3] += w * f1.y;
                    va[4] += w * f2.x; va[5] += w * f2.y;
                    va[6] += w * f3.x; va[7] += w * f3.y;
                }
                __syncthreads();
                if (tid == 0) {
                    int nx = c + 2;
                    unsigned dst = ring0 + st * STG;
                    if (nx < 8) {
                        mbar_expect_tx(mb, STG);
                        tma_ld(dst, vbase + (size_t)nx * STG, STG, mb);
                    } else if (s < STEPS - 2) {     // prefetch next pass keys
                        mbar_expect_tx(mb, STG);
                        tma_ld(dst, kbase + (size_t)(nx - 8) * STG, STG, mb);
                    }
                }
            }
            // merge tg-pairs within warp, then 32 warp partials
            #pragma unroll
            for (int j = 0; j < 8; j++)
                va[j] += __shfl_xor_sync(0xffffffffu, va[j], 16);
            if ((lane >> 4) == 0) {
                float4* cp = (float4*)(scr + wid * 128 + kc * 8);
                cp[0] = make_float4(va[0], va[1], va[2], va[3]);
                cp[1] = make_float4(va[4], va[5], va[6], va[7]);
            }
        }
        __syncthreads();

        // ctx -> s_x[0:128]; h_new -> s_x[128:428]
        if (tid < 128) {
            float inv = 1.f / s_bc[1];
            float acc = 0.f;
            #pragma unroll
            for (int w = 0; w < 32; w++) acc += scr[w * 128 + tid];
            s_x[tid] = acc * inv;
        }
        for (int i = tid; i < HD; i += NTHR) s_x[128 + i] = s_h[i];
        __syncthreads();
        CLUSTER_SYNC();    // x + char visible to partner for next LSTM
    }
}

// ---------------- host launcher ----------------
extern "C" void kernel_launch(void* const* d_in, const int* in_sizes, int n_in,
                              void* d_out, int out_size) {
    const float* keys   = (const float*)d_in[0];
    const float* values = (const float*)d_in[1];
    const float* emb    = (const float*)d_in[2];
    const float* W_phi  = (const float*)d_in[3];
    const float* b_phi  = (const float*)d_in[4];
    const float* W_ih   = (const float*)d_in[5];
    const float* b_ih   = (const float*)d_in[6];
    const float* W_hh   = (const float*)d_in[7];
    const float* b_hh   = (const float*)d_in[8];
    const float* W_proj = (const float*)d_in[9];
    const float* b_proj = (const float*)d_in[10];
    const float* h0     = (const float*)d_in[11];
    const float* c0     = (const float*)d_in[12];
    float* out = (float*)d_out;

    int write_preds = (out_size >= STEPS * BB * NV + STEPS * BB) ? 1 : 0;

    static int attr_done = 0;
    if (!attr_done) {
        cudaFuncSetAttribute(decoder_persistent,
                             cudaFuncAttributeMaxDynamicSharedMemorySize,
                             SMEM_BYTES);
        attr_done = 1;
    }

    init_kernel<<<NV + TRB + KTB + WQB, 256>>>(keys, values, emb, W_ih, b_ih,
                                               b_hh, W_hh);
    decoder_persistent<<<BB, NTHR, SMEM_BYTES>>>(W_phi, b_phi, W_proj, b_proj,
                                                 h0, c0, out, write_preds);
}